// round 14
// baseline (speedup 1.0000x reference)
#include <cuda_runtime.h>
#include <cuda_fp16.h>
#include <cstdint>

#define B_ 16
#define L_ 2048
#define D_ 128
#define MT 128             // query rows per item (32 per warp)
#define NT 32              // keys per tile
#define MTILES 16
#define NITEMS_A 512       // (batch, mtile, K-half)
#define NBM 256            // (batch, mtile)
#define NCHUNKS 4096       // 32768 rows / 8
#define NCTAS 296
#define TOT (B_ * L_ * D_)

#define STRB 272           // fp16 tile row stride in BYTES

// smem
#define SM_Q16   0         // 34816
#define SM_STAGE 34816
#define STG_K    0
#define STG_V    8704
#define STG_BYTES 17408
#define SMEM_BYTES (SM_STAGE + 4 * STG_BYTES)   // 104448 (2 CTAs/SM)

// ---- device scratch ----
__device__ __align__(16) static uint32_t g_k16[TOT / 2];
__device__ __align__(16) static uint32_t g_v16[TOT / 2];
__device__ __align__(16) static uint32_t g_pscr[(size_t)(B_ * L_ / 2) * L_]; // fp16 unnorm p
__device__ __align__(16) static float    g_ctxp[2 * (size_t)TOT];  // partial ctx per K-half
__device__ __align__(16) static float    g_sum[B_ * L_];           // row sums (atomic)
__device__ static int g_done[NBM];
__device__ static int g_ctrA;
__device__ static int g_ctrN;

__device__ __forceinline__ uint32_t smem_u32(const void* p) {
    uint32_t a;
    asm("{ .reg .u64 t; cvta.to.shared.u64 t, %1; cvt.u32.u64 %0, t; }" : "=r"(a) : "l"(p));
    return a;
}

#define CP16(SA, GA) \
    asm volatile("cp.async.cg.shared.global [%0], [%1], 16;" :: "r"(SA), "l"(GA) : "memory")
#define CP_COMMIT() asm volatile("cp.async.commit_group;" ::: "memory")
#define CP_WAIT(N)  asm volatile("cp.async.wait_group %0;" :: "n"(N) : "memory")

#define LDSM4(R0, R1, R2, R3, ADDR) \
    asm volatile("ldmatrix.sync.aligned.m8n8.x4.shared.b16 {%0,%1,%2,%3}, [%4];" \
        : "=r"(R0), "=r"(R1), "=r"(R2), "=r"(R3) : "r"(ADDR))

#define LDSM4T(R0, R1, R2, R3, ADDR) \
    asm volatile("ldmatrix.sync.aligned.m8n8.x4.trans.shared.b16 {%0,%1,%2,%3}, [%4];" \
        : "=r"(R0), "=r"(R1), "=r"(R2), "=r"(R3) : "r"(ADDR))

#define MMA_F16(D, A0, A1, A2, A3, B0, B1) \
    asm volatile("mma.sync.aligned.m16n8k16.row.col.f32.f16.f16.f32 " \
        "{%0,%1,%2,%3}, {%4,%5,%6,%7}, {%8,%9}, {%0,%1,%2,%3};" \
        : "+f"((D)[0]), "+f"((D)[1]), "+f"((D)[2]), "+f"((D)[3]) \
        : "r"(A0), "r"(A1), "r"(A2), "r"(A3), "r"(B0), "r"(B1))

__device__ __forceinline__ float ex2(float x) {
    float r;
    asm("ex2.approx.f32 %0, %1;" : "=f"(r) : "f"(x));
    return r;
}
__device__ __forceinline__ uint32_t cvt_h2(float x0, float x1) {
    uint32_t d;
    asm("cvt.rn.f16x2.f32 %0, %1, %2;" : "=r"(d) : "f"(x1), "f"(x0));
    return d;
}

// ============================================================================
// Kernel 0: convert K/V to fp16 scratch + zero counters/sums/flags (~9us)
// ============================================================================
__global__ void __launch_bounds__(256)
split_kv_kernel(const float* __restrict__ k, const float* __restrict__ v)
{
    const size_t i4 = (size_t)blockIdx.x * 256 + threadIdx.x;
    const float4 kx = ((const float4*)k)[i4];
    const float4 vx = ((const float4*)v)[i4];
    uint2 kh, vh;
    kh.x = cvt_h2(kx.x, kx.y);  kh.y = cvt_h2(kx.z, kx.w);
    vh.x = cvt_h2(vx.x, vx.y);  vh.y = cvt_h2(vx.z, vx.w);
    ((uint2*)g_k16)[i4] = kh;
    ((uint2*)g_v16)[i4] = vh;

    // per-launch reinit (graph replays!)
    if (i4 < B_ * L_) g_sum[i4] = 0.0f;
    if (i4 < NBM)     g_done[i4] = 0;
    if (i4 == 0)      { g_ctrA = 0; g_ctrN = 0; }
}

// prefetch one 32-key tile (K16,V16): 512 chunks x 2 tensors, 8/thread
__device__ __forceinline__ void prefetch_tile(uint32_t st_base, size_t gelem, int t)
{
    const unsigned long long kg = (unsigned long long)__cvta_generic_to_global(g_k16);
    const unsigned long long vg = (unsigned long long)__cvta_generic_to_global(g_v16);
    #pragma unroll
    for (int j = 0; j < 4; ++j) {
        const int c   = t + j * 128;
        const int row = c >> 4;
        const int col = c & 15;
        const uint32_t so = (uint32_t)row * STRB + (uint32_t)col * 16;
        const unsigned long long go = ((unsigned long long)(gelem + (size_t)row * D_) + col * 8) * 2;
        CP16(st_base + STG_K + so, kg + go);
        CP16(st_base + STG_V + so, vg + go);
    }
}

// ============================================================================
// Kernel 1: 296 persistent CTAs (128 thr, occ 2). Phase 1: work-steal 512
// attn K-half items (pscr + partial ctx + atomic row sums). Phase 2: work-
// steal 4096 norm chunks (8 rows: probs fp16->fp32 * inv, ctx combine).
// ============================================================================
__global__ void __launch_bounds__(128, 2)
attn_fused_kernel(const float* __restrict__ q,
                  float* __restrict__ ctx,
                  float* __restrict__ probs)
{
    extern __shared__ char smem[];
    const uint32_t sb = smem_u32(smem);
    const uint32_t Q16 = sb + SM_Q16;
    __shared__ int s_work;

    const int t   = threadIdx.x;
    const int wid = t >> 5;
    const int lid = t & 31;

    const float SL = 0.08838834764831845f * 1.4426950408889634f;

    const uint32_t q_off0 = (uint32_t)(wid * 32 + (lid & 15)) * STRB + (uint32_t)(lid >> 4) * 16;
    const uint32_t q_off1 = q_off0 + 16u * STRB;
    const uint32_t k_off  = (uint32_t)((lid & 7) + ((lid >> 4) << 3)) * STRB
                          + (uint32_t)((lid >> 3) & 1) * 16;
    const uint32_t v_off  = (uint32_t)((lid & 7) + (((lid >> 3) & 1) << 3)) * STRB
                          + (uint32_t)(lid >> 4) * 16;

    // ================= Phase 1: attn items =================
    for (;;) {
        __syncthreads();
        if (t == 0) s_work = atomicAdd(&g_ctrA, 1);
        __syncthreads();
        const int item = s_work;
        if (item >= NITEMS_A) break;

        const int bm     = item >> 1;
        const int kh     = item & 1;
        const int b      = bm >> 4;
        const int m_base = (bm & 15) * MT;
        const size_t bL  = (size_t)b * L_;
        const float* qb  = q + (bL + m_base) * D_;
        const size_t kvb = bL * D_;
        const int tb     = kh * 32;                  // tile base
        const int start  = (bm & 3) * 8;             // stagger within 32

        // prologue: prefetch 3 tiles
        #pragma unroll
        for (int pi = 0; pi < 3; ++pi) {
            const int kt = tb + ((start + pi) & 31);
            prefetch_tile(sb + SM_STAGE + (uint32_t)pi * STG_BYTES,
                          kvb + (size_t)(kt * NT) * D_, t);
            CP_COMMIT();
        }

        // Q load/convert (pre-scaled), one row per thread
        {
            const float4* src = (const float4*)(qb + (size_t)t * D_);
            char* dh = smem + SM_Q16 + t * STRB;
            #pragma unroll
            for (int cc = 0; cc < 16; ++cc) {
                const float4 x0 = src[2 * cc];
                const float4 x1 = src[2 * cc + 1];
                uint4 H;
                H.x = cvt_h2(x0.x * SL, x0.y * SL);
                H.y = cvt_h2(x0.z * SL, x0.w * SL);
                H.z = cvt_h2(x1.x * SL, x1.y * SL);
                H.w = cvt_h2(x1.z * SL, x1.w * SL);
                *(uint4*)(dh + cc * 16) = H;
            }
        }

        float C[2][16][4];
        #pragma unroll
        for (int mf = 0; mf < 2; ++mf)
            #pragma unroll
            for (int f = 0; f < 16; ++f)
                #pragma unroll
                for (int e = 0; e < 4; ++e) C[mf][f][e] = 0.0f;
        float rs[2][2] = {{0.f, 0.f}, {0.f, 0.f}};

        for (int i = 0; i < 32; ++i) {
            const int kt   = tb + ((start + i) & 31);
            const int key0 = kt * NT;
            const uint32_t stg = sb + SM_STAGE + (uint32_t)(i & 3) * STG_BYTES;

            CP_WAIT(2);
            __syncthreads();

            if (i + 3 < 32) {
                const int nt = tb + ((start + i + 3) & 31);
                prefetch_tile(sb + SM_STAGE + (uint32_t)((i + 3) & 3) * STG_BYTES,
                              kvb + (size_t)(nt * NT) * D_, t);
            }
            CP_COMMIT();

            const uint32_t KHI = stg + STG_K;
            const uint32_t VHI = stg + STG_V;

            // QK
            float S[2][4][4];
            #pragma unroll
            for (int mf = 0; mf < 2; ++mf)
                #pragma unroll
                for (int f = 0; f < 4; ++f)
                    #pragma unroll
                    for (int e = 0; e < 4; ++e) S[mf][f][e] = 0.0f;

            #pragma unroll
            for (int ks = 0; ks < 8; ++ks) {
                uint32_t a0[4], a1[4], bh[8];
                LDSM4(a0[0], a0[1], a0[2], a0[3], Q16 + q_off0 + ks * 32);
                LDSM4(a1[0], a1[1], a1[2], a1[3], Q16 + q_off1 + ks * 32);
                #pragma unroll
                for (int j = 0; j < 2; ++j)
                    LDSM4(bh[4*j], bh[4*j+1], bh[4*j+2], bh[4*j+3],
                          KHI + k_off + (uint32_t)j * (16 * STRB) + ks * 32);
                #pragma unroll
                for (int j = 0; j < 2; ++j) {
                    MMA_F16(S[0][2*j],   a0[0], a0[1], a0[2], a0[3], bh[4*j],   bh[4*j+1]);
                    MMA_F16(S[0][2*j+1], a0[0], a0[1], a0[2], a0[3], bh[4*j+2], bh[4*j+3]);
                    MMA_F16(S[1][2*j],   a1[0], a1[1], a1[2], a1[3], bh[4*j],   bh[4*j+1]);
                    MMA_F16(S[1][2*j+1], a1[0], a1[1], a1[2], a1[3], bh[4*j+2], bh[4*j+3]);
                }
            }

            // exp + pscr fp16 store + pack P16
            uint32_t PH[2][2][4];
            #pragma unroll
            for (int mf = 0; mf < 2; ++mf) {
                uint32_t* prow = g_pscr
                    + (((size_t)(bL + m_base + 32 * wid + 16 * mf + (lid >> 2))) * L_
                       + key0 + 2 * (lid & 3)) / 2;
                #pragma unroll
                for (int f = 0; f < 4; ++f) {
                    const float p0 = ex2(S[mf][f][0]);
                    const float p1 = ex2(S[mf][f][1]);
                    const float p2 = ex2(S[mf][f][2]);
                    const float p3 = ex2(S[mf][f][3]);
                    rs[mf][0] += p0 + p1;
                    rs[mf][1] += p2 + p3;
                    const int ks = f >> 1;
                    const int hh = (f & 1) * 2;
                    PH[mf][ks][hh]     = cvt_h2(p0, p1);
                    PH[mf][ks][hh + 1] = cvt_h2(p2, p3);
                    prow[4 * f]          = PH[mf][ks][hh];
                    prow[4 * L_ + 4 * f] = PH[mf][ks][hh + 1];
                }
            }

            // PV
            #pragma unroll
            for (int ks = 0; ks < 2; ++ks) {
                uint32_t vf[32];
                #pragma unroll
                for (int j = 0; j < 8; ++j)
                    LDSM4T(vf[4*j], vf[4*j+1], vf[4*j+2], vf[4*j+3],
                           VHI + v_off + (uint32_t)ks * (16 * STRB) + j * 32);
                #pragma unroll
                for (int j = 0; j < 8; ++j) {
                    MMA_F16(C[0][2*j],   PH[0][ks][0], PH[0][ks][1], PH[0][ks][2], PH[0][ks][3], vf[4*j],   vf[4*j+1]);
                    MMA_F16(C[0][2*j+1], PH[0][ks][0], PH[0][ks][1], PH[0][ks][2], PH[0][ks][3], vf[4*j+2], vf[4*j+3]);
                    MMA_F16(C[1][2*j],   PH[1][ks][0], PH[1][ks][1], PH[1][ks][2], PH[1][ks][3], vf[4*j],   vf[4*j+1]);
                    MMA_F16(C[1][2*j+1], PH[1][ks][0], PH[1][ks][1], PH[1][ks][2], PH[1][ks][3], vf[4*j+2], vf[4*j+3]);
                }
            }
        }
        CP_WAIT(0);   // drain before next item overwrites stages

        // epilogue: partial sums (atomic) + raw partial ctx -> g_ctxp[kh]
        float* ctxp = g_ctxp + (size_t)(item & 1) * TOT;
        #pragma unroll
        for (int mf = 0; mf < 2; ++mf) {
            float r0 = rs[mf][0], r1 = rs[mf][1];
            r0 += __shfl_xor_sync(0xffffffffu, r0, 1);
            r0 += __shfl_xor_sync(0xffffffffu, r0, 2);
            r1 += __shfl_xor_sync(0xffffffffu, r1, 1);
            r1 += __shfl_xor_sync(0xffffffffu, r1, 2);

            const int row0 = m_base + 32 * wid + 16 * mf + (lid >> 2);
            if ((lid & 3) == 0) {
                atomicAdd(&g_sum[bL + row0],     r0);
                atomicAdd(&g_sum[bL + row0 + 8], r1);
            }

            float* crow = ctxp + ((size_t)(bL + row0)) * D_ + 2 * (lid & 3);
            #pragma unroll
            for (int f = 0; f < 16; ++f) {
                *(float2*)(crow + 8 * f)          = make_float2(C[mf][f][0], C[mf][f][1]);
                *(float2*)(crow + 8 * D_ + 8 * f) = make_float2(C[mf][f][2], C[mf][f][3]);
            }
        }
        __threadfence();
        __syncthreads();
        if (t == 0) atomicAdd(&g_done[bm], 1);
    }

    // ================= Phase 2: norm chunks =================
    const int rr = t >> 4;     // 0..7  (row within chunk)
    const int cc = t & 15;     // 0..15 (16B column group)
    for (;;) {
        __syncthreads();
        if (t == 0) s_work = atomicAdd(&g_ctrN, 1);
        __syncthreads();
        const int c = s_work;
        if (c >= NCHUNKS) break;
        const int bm = c >> 4;
        if (t == 0) {
            while (atomicAdd(&g_done[bm], 0) < 2) {}
            __threadfence();
        }
        __syncthreads();

        const int row = c * 8 + rr;                       // global row
        const float inv = 1.0f / g_sum[row];

        const uint4* psrc = (const uint4*)g_pscr + (size_t)row * 256 + cc;
        float* pdst = probs + (size_t)row * L_ + cc * 8;
        #pragma unroll
        for (int bb = 0; bb < 2; ++bb) {
            uint4 d[8];
            #pragma unroll
            for (int j = 0; j < 8; ++j) d[j] = psrc[(bb * 8 + j) * 16];
            #pragma unroll
            for (int j = 0; j < 8; ++j) {
                const float2 f0 = __half22float2(*(const __half2*)&d[j].x);
                const float2 f1 = __half22float2(*(const __half2*)&d[j].y);
                const float2 f2 = __half22float2(*(const __half2*)&d[j].z);
                const float2 f3 = __half22float2(*(const __half2*)&d[j].w);
                float* o = pdst + (bb * 8 + j) * 128;
                *(float4*)o       = make_float4(f0.x * inv, f0.y * inv, f1.x * inv, f1.y * inv);
                *(float4*)(o + 4) = make_float4(f2.x * inv, f2.y * inv, f3.x * inv, f3.y * inv);
            }
        }
        // ctx: combine halves, scale
        const float4* cp0 = (const float4*)(g_ctxp + (size_t)row * D_) + cc * 2;
        const float4* cp1 = (const float4*)(g_ctxp + (size_t)TOT + (size_t)row * D_) + cc * 2;
        float4* cdst = (float4*)(ctx + (size_t)row * D_) + cc * 2;
        #pragma unroll
        for (int j = 0; j < 2; ++j) {
            const float4 a = cp0[j];
            const float4 bb2 = cp1[j];
            cdst[j] = make_float4((a.x + bb2.x) * inv, (a.y + bb2.y) * inv,
                                  (a.z + bb2.z) * inv, (a.w + bb2.w) * inv);
        }
    }
}

extern "C" void kernel_launch(void* const* d_in, const int* in_sizes, int n_in,
                              void* d_out, int out_size)
{
    const float* q = (const float*)d_in[0];
    const float* k = (const float*)d_in[1];
    const float* v = (const float*)d_in[2];

    float* out   = (float*)d_out;
    float* ctx   = out;
    float* probs = out + (size_t)B_ * L_ * D_;

    cudaFuncSetAttribute(attn_fused_kernel,
                         cudaFuncAttributeMaxDynamicSharedMemorySize, SMEM_BYTES);

    split_kv_kernel<<<TOT / 4 / 256, 256>>>(k, v);

    attn_fused_kernel<<<NCTAS, 128, SMEM_BYTES>>>(q, ctx, probs);
}

// round 15
// speedup vs baseline: 1.1063x; 1.1063x over previous
#include <cuda_runtime.h>
#include <cuda_fp16.h>
#include <cstdint>

#define B_ 16
#define L_ 2048
#define D_ 128
#define MT 128             // query rows per item (32 per warp)
#define NT 32              // keys per tile
#define NTILES 64
#define MTILES 16
#define NITEMS (B_ * MTILES)   // 256
#define TOT (B_ * L_ * D_)

#define NA 148             // attnA items (one wave, 1 CTA/SM)
#define NB (NITEMS - NA)   // 108

#define STRB 272           // fp16 tile row stride in BYTES

// smem byte offsets
#define SM_Q16   0         // 34816
#define SM_STAGE 34816
#define STG_K    0
#define STG_V    8704
#define STG_BYTES 17408
#define SMEM_BYTES (SM_STAGE + 4 * STG_BYTES)   // 104448

// ---- device scratch ----
__device__ __align__(16) static uint32_t g_k16[TOT / 2];
__device__ __align__(16) static uint32_t g_v16[TOT / 2];
__device__ __align__(16) static uint32_t g_pscr[(size_t)(B_ * L_ / 2) * L_]; // fp16 unnorm p
__device__ __align__(16) static float    g_inv[B_ * L_];   // per-row 1/sum

__device__ __forceinline__ uint32_t smem_u32(const void* p) {
    uint32_t a;
    asm("{ .reg .u64 t; cvta.to.shared.u64 t, %1; cvt.u32.u64 %0, t; }" : "=r"(a) : "l"(p));
    return a;
}

#define CP16(SA, GA) \
    asm volatile("cp.async.cg.shared.global [%0], [%1], 16;" :: "r"(SA), "l"(GA) : "memory")
#define CP_COMMIT() asm volatile("cp.async.commit_group;" ::: "memory")
#define CP_WAIT(N)  asm volatile("cp.async.wait_group %0;" :: "n"(N) : "memory")

#define LDSM4(R0, R1, R2, R3, ADDR) \
    asm volatile("ldmatrix.sync.aligned.m8n8.x4.shared.b16 {%0,%1,%2,%3}, [%4];" \
        : "=r"(R0), "=r"(R1), "=r"(R2), "=r"(R3) : "r"(ADDR))

#define LDSM4T(R0, R1, R2, R3, ADDR) \
    asm volatile("ldmatrix.sync.aligned.m8n8.x4.trans.shared.b16 {%0,%1,%2,%3}, [%4];" \
        : "=r"(R0), "=r"(R1), "=r"(R2), "=r"(R3) : "r"(ADDR))

#define MMA_F16(D, A0, A1, A2, A3, B0, B1) \
    asm volatile("mma.sync.aligned.m16n8k16.row.col.f32.f16.f16.f32 " \
        "{%0,%1,%2,%3}, {%4,%5,%6,%7}, {%8,%9}, {%0,%1,%2,%3};" \
        : "+f"((D)[0]), "+f"((D)[1]), "+f"((D)[2]), "+f"((D)[3]) \
        : "r"(A0), "r"(A1), "r"(A2), "r"(A3), "r"(B0), "r"(B1))

__device__ __forceinline__ float ex2(float x) {
    float r;
    asm("ex2.approx.f32 %0, %1;" : "=f"(r) : "f"(x));
    return r;
}
__device__ __forceinline__ uint32_t cvt_h2(float x0, float x1) {
    uint32_t d;
    asm("cvt.rn.f16x2.f32 %0, %1, %2;" : "=r"(d) : "f"(x1), "f"(x0));
    return d;
}

// ============================================================================
// Kernel 0: convert K and V to fp16 scratch (~9us, DRAM-bound)
// ============================================================================
__global__ void __launch_bounds__(256)
split_kv_kernel(const float* __restrict__ k, const float* __restrict__ v)
{
    const size_t i4 = (size_t)blockIdx.x * 256 + threadIdx.x;
    const float4 kx = ((const float4*)k)[i4];
    const float4 vx = ((const float4*)v)[i4];
    uint2 kh, vh;
    kh.x = cvt_h2(kx.x, kx.y);  kh.y = cvt_h2(kx.z, kx.w);
    vh.x = cvt_h2(vx.x, vx.y);  vh.y = cvt_h2(vx.z, vx.w);
    ((uint2*)g_k16)[i4] = kh;
    ((uint2*)g_v16)[i4] = vh;
}

// prefetch one 32-key tile (K16,V16): 512 chunks x 2 tensors, 8/thread
__device__ __forceinline__ void prefetch_tile(uint32_t st_base, size_t gelem, int t)
{
    const unsigned long long kg = (unsigned long long)__cvta_generic_to_global(g_k16);
    const unsigned long long vg = (unsigned long long)__cvta_generic_to_global(g_v16);
    #pragma unroll
    for (int j = 0; j < 4; ++j) {
        const int c   = t + j * 128;
        const int row = c >> 4;
        const int col = c & 15;
        const uint32_t so = (uint32_t)row * STRB + (uint32_t)col * 16;
        const unsigned long long go = ((unsigned long long)(gelem + (size_t)row * D_) + col * 8) * 2;
        CP16(st_base + STG_K + so, kg + go);
        CP16(st_base + STG_V + so, vg + go);
    }
}

// ============================================================================
// Kernel 1: item = (batch, 128 q-rows), item index = blockIdx.x + item_base.
// 128 threads, 32 rows/warp, fp16 GEMMs, 4-stage cp.async, 1 barrier/tile.
// Writes fp16 unnormalized p -> g_pscr, ctx (normalized), g_inv.
// ============================================================================
__global__ void __launch_bounds__(128, 2)
attn_mma_kernel(const float* __restrict__ q,
                float* __restrict__ ctx,
                int item_base)
{
    extern __shared__ char smem[];
    const uint32_t sb = smem_u32(smem);
    const uint32_t Q16 = sb + SM_Q16;

    const int t   = threadIdx.x;
    const int wid = t >> 5;
    const int lid = t & 31;

    const float SL = 0.08838834764831845f * 1.4426950408889634f;

    const uint32_t q_off0 = (uint32_t)(wid * 32 + (lid & 15)) * STRB + (uint32_t)(lid >> 4) * 16;
    const uint32_t q_off1 = q_off0 + 16u * STRB;
    const uint32_t k_off  = (uint32_t)((lid & 7) + ((lid >> 4) << 3)) * STRB
                          + (uint32_t)((lid >> 3) & 1) * 16;
    const uint32_t v_off  = (uint32_t)((lid & 7) + (((lid >> 3) & 1) << 3)) * STRB
                          + (uint32_t)(lid >> 4) * 16;

    const int item   = (int)blockIdx.x + item_base;
    const int b      = item >> 4;
    const int m_base = (item & 15) * MT;
    const size_t bL  = (size_t)b * L_;
    const float* qb  = q + (bL + m_base) * D_;
    const size_t kvb = bL * D_;

    const int start = (item & 3) << 4;   // 0,16,32,48

    #pragma unroll
    for (int pi = 0; pi < 3; ++pi) {
        const int ptile = (start + pi) & (NTILES - 1);
        prefetch_tile(sb + SM_STAGE + (uint32_t)pi * STG_BYTES,
                      kvb + (size_t)(ptile * NT) * D_, t);
        CP_COMMIT();
    }

    // Q load/convert, pre-scaled
    {
        const float4* src = (const float4*)(qb + (size_t)t * D_);
        char* dh = smem + SM_Q16 + t * STRB;
        #pragma unroll
        for (int cc = 0; cc < 16; ++cc) {
            const float4 x0 = src[2 * cc];
            const float4 x1 = src[2 * cc + 1];
            uint4 H;
            H.x = cvt_h2(x0.x * SL, x0.y * SL);
            H.y = cvt_h2(x0.z * SL, x0.w * SL);
            H.z = cvt_h2(x1.x * SL, x1.y * SL);
            H.w = cvt_h2(x1.z * SL, x1.w * SL);
            *(uint4*)(dh + cc * 16) = H;
        }
    }

    float C[2][16][4];
    #pragma unroll
    for (int mf = 0; mf < 2; ++mf)
        #pragma unroll
        for (int f = 0; f < 16; ++f)
            #pragma unroll
            for (int e = 0; e < 4; ++e) C[mf][f][e] = 0.0f;
    float rs[2][2] = {{0.f, 0.f}, {0.f, 0.f}};

    for (int i = 0; i < NTILES; ++i) {
        const int tile = (start + i) & (NTILES - 1);
        const int key0 = tile * NT;
        const uint32_t stg = sb + SM_STAGE + (uint32_t)(i & 3) * STG_BYTES;

        CP_WAIT(2);
        __syncthreads();

        if (i + 3 < NTILES) {
            const int ntile = (start + i + 3) & (NTILES - 1);
            prefetch_tile(sb + SM_STAGE + (uint32_t)((i + 3) & 3) * STG_BYTES,
                          kvb + (size_t)(ntile * NT) * D_, t);
        }
        CP_COMMIT();

        const uint32_t KHI = stg + STG_K;
        const uint32_t VHI = stg + STG_V;

        // QK
        float S[2][4][4];
        #pragma unroll
        for (int mf = 0; mf < 2; ++mf)
            #pragma unroll
            for (int f = 0; f < 4; ++f)
                #pragma unroll
                for (int e = 0; e < 4; ++e) S[mf][f][e] = 0.0f;

        #pragma unroll
        for (int ks = 0; ks < 8; ++ks) {
            uint32_t a0[4], a1[4], bh[8];
            LDSM4(a0[0], a0[1], a0[2], a0[3], Q16 + q_off0 + ks * 32);
            LDSM4(a1[0], a1[1], a1[2], a1[3], Q16 + q_off1 + ks * 32);
            #pragma unroll
            for (int j = 0; j < 2; ++j)
                LDSM4(bh[4*j], bh[4*j+1], bh[4*j+2], bh[4*j+3],
                      KHI + k_off + (uint32_t)j * (16 * STRB) + ks * 32);
            #pragma unroll
            for (int j = 0; j < 2; ++j) {
                MMA_F16(S[0][2*j],   a0[0], a0[1], a0[2], a0[3], bh[4*j],   bh[4*j+1]);
                MMA_F16(S[0][2*j+1], a0[0], a0[1], a0[2], a0[3], bh[4*j+2], bh[4*j+3]);
                MMA_F16(S[1][2*j],   a1[0], a1[1], a1[2], a1[3], bh[4*j],   bh[4*j+1]);
                MMA_F16(S[1][2*j+1], a1[0], a1[1], a1[2], a1[3], bh[4*j+2], bh[4*j+3]);
            }
        }

        // exp + fp16 scratch write + pack P16
        uint32_t PH[2][2][4];
        #pragma unroll
        for (int mf = 0; mf < 2; ++mf) {
            uint32_t* prow = g_pscr
                + (((size_t)(bL + m_base + 32 * wid + 16 * mf + (lid >> 2))) * L_
                   + key0 + 2 * (lid & 3)) / 2;
            #pragma unroll
            for (int f = 0; f < 4; ++f) {
                const float p0 = ex2(S[mf][f][0]);
                const float p1 = ex2(S[mf][f][1]);
                const float p2 = ex2(S[mf][f][2]);
                const float p3 = ex2(S[mf][f][3]);
                rs[mf][0] += p0 + p1;
                rs[mf][1] += p2 + p3;
                const int ks = f >> 1;
                const int hh = (f & 1) * 2;
                PH[mf][ks][hh]     = cvt_h2(p0, p1);
                PH[mf][ks][hh + 1] = cvt_h2(p2, p3);
                prow[4 * f]          = PH[mf][ks][hh];
                prow[4 * L_ + 4 * f] = PH[mf][ks][hh + 1];
            }
        }

        // PV
        #pragma unroll
        for (int ks = 0; ks < 2; ++ks) {
            uint32_t vf[32];
            #pragma unroll
            for (int j = 0; j < 8; ++j)
                LDSM4T(vf[4*j], vf[4*j+1], vf[4*j+2], vf[4*j+3],
                       VHI + v_off + (uint32_t)ks * (16 * STRB) + j * 32);
            #pragma unroll
            for (int j = 0; j < 8; ++j) {
                MMA_F16(C[0][2*j],   PH[0][ks][0], PH[0][ks][1], PH[0][ks][2], PH[0][ks][3], vf[4*j],   vf[4*j+1]);
                MMA_F16(C[0][2*j+1], PH[0][ks][0], PH[0][ks][1], PH[0][ks][2], PH[0][ks][3], vf[4*j+2], vf[4*j+3]);
                MMA_F16(C[1][2*j],   PH[1][ks][0], PH[1][ks][1], PH[1][ks][2], PH[1][ks][3], vf[4*j],   vf[4*j+1]);
                MMA_F16(C[1][2*j+1], PH[1][ks][0], PH[1][ks][1], PH[1][ks][2], PH[1][ks][3], vf[4*j+2], vf[4*j+3]);
            }
        }
    }

    // row sums + normalize ctx + store inv sums
    #pragma unroll
    for (int mf = 0; mf < 2; ++mf) {
        float r0 = rs[mf][0], r1 = rs[mf][1];
        r0 += __shfl_xor_sync(0xffffffffu, r0, 1);
        r0 += __shfl_xor_sync(0xffffffffu, r0, 2);
        r1 += __shfl_xor_sync(0xffffffffu, r1, 1);
        r1 += __shfl_xor_sync(0xffffffffu, r1, 2);
        const float inv0 = 1.0f / r0;
        const float inv1 = 1.0f / r1;

        const int row0 = m_base + 32 * wid + 16 * mf + (lid >> 2);
        if ((lid & 3) == 0) {
            g_inv[bL + row0]     = inv0;
            g_inv[bL + row0 + 8] = inv1;
        }

        float* crow = ctx + ((size_t)(bL + row0)) * D_ + 2 * (lid & 3);
        #pragma unroll
        for (int f = 0; f < 16; ++f) {
            *(float2*)(crow + 8 * f)          = make_float2(C[mf][f][0] * inv0, C[mf][f][1] * inv0);
            *(float2*)(crow + 8 * D_ + 8 * f) = make_float2(C[mf][f][2] * inv1, C[mf][f][3] * inv1);
        }
    }
}

// ============================================================================
// Kernel 2: streaming normalize: probs = fp16_scratch * inv[row] -> fp32.
// One block per row; row = blockIdx.x + row_base.
// ============================================================================
__global__ void __launch_bounds__(256)
norm_probs_kernel(float* __restrict__ probs, int row_base)
{
    const size_t rowi = (size_t)((int)blockIdx.x + row_base);
    const int t = threadIdx.x;
    const float inv = g_inv[rowi];

    const uint4 d = ((const uint4*)(g_pscr + rowi * (L_ / 2)))[t];
    float2 f0 = __half22float2(*(const __half2*)&d.x);
    float2 f1 = __half22float2(*(const __half2*)&d.y);
    float2 f2 = __half22float2(*(const __half2*)&d.z);
    float2 f3 = __half22float2(*(const __half2*)&d.w);

    float4 o0, o1;
    o0.x = f0.x * inv; o0.y = f0.y * inv; o0.z = f1.x * inv; o0.w = f1.y * inv;
    o1.x = f2.x * inv; o1.y = f2.y * inv; o1.z = f3.x * inv; o1.w = f3.y * inv;

    float* drow = probs + rowi * (size_t)L_ + t * 8;
    *(float4*)(drow)     = o0;
    *(float4*)(drow + 4) = o1;
}

// cached side stream + events (created once; creation is not device-mem alloc)
struct PipeRes {
    cudaStream_t side;
    cudaEvent_t eA, eB, eN;
    PipeRes() {
        cudaStreamCreateWithFlags(&side, cudaStreamNonBlocking);
        cudaEventCreateWithFlags(&eA, cudaEventDisableTiming);
        cudaEventCreateWithFlags(&eB, cudaEventDisableTiming);
        cudaEventCreateWithFlags(&eN, cudaEventDisableTiming);
    }
};

extern "C" void kernel_launch(void* const* d_in, const int* in_sizes, int n_in,
                              void* d_out, int out_size)
{
    static PipeRes R;   // constructed on first call, reused (same work every call)

    const float* q = (const float*)d_in[0];
    const float* k = (const float*)d_in[1];
    const float* v = (const float*)d_in[2];

    float* out   = (float*)d_out;
    float* ctx   = out;
    float* probs = out + (size_t)B_ * L_ * D_;

    cudaFuncSetAttribute(attn_mma_kernel,
                         cudaFuncAttributeMaxDynamicSharedMemorySize, SMEM_BYTES);

    // main stream (default): split -> attnA -> attnB
    split_kv_kernel<<<TOT / 4 / 256, 256>>>(k, v);

    attn_mma_kernel<<<NA, 128, SMEM_BYTES>>>(q, ctx, 0);
    cudaEventRecord(R.eA, 0);

    attn_mma_kernel<<<NB, 128, SMEM_BYTES>>>(q, ctx, NA);
    cudaEventRecord(R.eB, 0);

    // side stream: normA (overlaps attnB), then normB after attnB
    cudaStreamWaitEvent(R.side, R.eA, 0);
    norm_probs_kernel<<<NA * MT, 256, 0, R.side>>>(probs, 0);
    cudaStreamWaitEvent(R.side, R.eB, 0);
    norm_probs_kernel<<<NB * MT, 256, 0, R.side>>>(probs, NA * MT);
    cudaEventRecord(R.eN, R.side);

    // join back to main stream
    cudaStreamWaitEvent(0, R.eN, 0);
}

// round 16
// speedup vs baseline: 1.1404x; 1.0308x over previous
#include <cuda_runtime.h>
#include <cuda_fp16.h>
#include <cstdint>

#define B_ 16
#define L_ 2048
#define D_ 128
#define NT 32              // keys per tile
#define NTILES 64
#define NCTAS 296          // 2 per SM, one wave
#define TOT (B_ * L_ * D_)

#define STRB 272           // fp16 tile row stride in BYTES

// smem byte offsets
#define SM_Q16   0         // 128 rows x 272B = 34816 (32 rows per warp)
#define SM_STAGE 34816
#define STG_K    0
#define STG_V    8704
#define STG_BYTES 17408
#define SMEM_BYTES (SM_STAGE + 4 * STG_BYTES)   // 104448 (2 CTAs/SM)

// ---- device scratch ----
__device__ __align__(16) static uint32_t g_k16[TOT / 2];
__device__ __align__(16) static uint32_t g_v16[TOT / 2];
__device__ __align__(16) static uint32_t g_pscr[(size_t)(B_ * L_ / 2) * L_]; // fp16 unnorm p
__device__ __align__(16) static float    g_inv[B_ * L_];   // per-row 1/sum

__device__ __forceinline__ uint32_t smem_u32(const void* p) {
    uint32_t a;
    asm("{ .reg .u64 t; cvta.to.shared.u64 t, %1; cvt.u32.u64 %0, t; }" : "=r"(a) : "l"(p));
    return a;
}

#define CP16(SA, GA) \
    asm volatile("cp.async.cg.shared.global [%0], [%1], 16;" :: "r"(SA), "l"(GA) : "memory")
#define CP_COMMIT() asm volatile("cp.async.commit_group;" ::: "memory")
#define CP_WAIT(N)  asm volatile("cp.async.wait_group %0;" :: "n"(N) : "memory")

#define LDSM4(R0, R1, R2, R3, ADDR) \
    asm volatile("ldmatrix.sync.aligned.m8n8.x4.shared.b16 {%0,%1,%2,%3}, [%4];" \
        : "=r"(R0), "=r"(R1), "=r"(R2), "=r"(R3) : "r"(ADDR))

#define LDSM4T(R0, R1, R2, R3, ADDR) \
    asm volatile("ldmatrix.sync.aligned.m8n8.x4.trans.shared.b16 {%0,%1,%2,%3}, [%4];" \
        : "=r"(R0), "=r"(R1), "=r"(R2), "=r"(R3) : "r"(ADDR))

#define MMA_F16(D, A0, A1, A2, A3, B0, B1) \
    asm volatile("mma.sync.aligned.m16n8k16.row.col.f32.f16.f16.f32 " \
        "{%0,%1,%2,%3}, {%4,%5,%6,%7}, {%8,%9}, {%0,%1,%2,%3};" \
        : "+f"((D)[0]), "+f"((D)[1]), "+f"((D)[2]), "+f"((D)[3]) \
        : "r"(A0), "r"(A1), "r"(A2), "r"(A3), "r"(B0), "r"(B1))

__device__ __forceinline__ float ex2(float x) {
    float r;
    asm("ex2.approx.f32 %0, %1;" : "=f"(r) : "f"(x));
    return r;
}
__device__ __forceinline__ uint32_t cvt_h2(float x0, float x1) {
    uint32_t d;
    asm("cvt.rn.f16x2.f32 %0, %1, %2;" : "=r"(d) : "f"(x1), "f"(x0));
    return d;
}

// ============================================================================
// Kernel 0: convert K and V to fp16 scratch (~9us, DRAM-bound)
// ============================================================================
__global__ void __launch_bounds__(256)
split_kv_kernel(const float* __restrict__ k, const float* __restrict__ v)
{
    const size_t i4 = (size_t)blockIdx.x * 256 + threadIdx.x;
    const float4 kx = ((const float4*)k)[i4];
    const float4 vx = ((const float4*)v)[i4];
    uint2 kh, vh;
    kh.x = cvt_h2(kx.x, kx.y);  kh.y = cvt_h2(kx.z, kx.w);
    vh.x = cvt_h2(vx.x, vx.y);  vh.y = cvt_h2(vx.z, vx.w);
    ((uint2*)g_k16)[i4] = kh;
    ((uint2*)g_v16)[i4] = vh;
}

// prefetch one 32-key tile (K16,V16): 512 chunks x 2 tensors, 8/thread
__device__ __forceinline__ void prefetch_tile(uint32_t st_base, size_t gelem, int t)
{
    const unsigned long long kg = (unsigned long long)__cvta_generic_to_global(g_k16);
    const unsigned long long vg = (unsigned long long)__cvta_generic_to_global(g_v16);
    #pragma unroll
    for (int j = 0; j < 4; ++j) {
        const int c   = t + j * 128;
        const int row = c >> 4;
        const int col = c & 15;
        const uint32_t so = (uint32_t)row * STRB + (uint32_t)col * 16;
        const unsigned long long go = ((unsigned long long)(gelem + (size_t)row * D_) + col * 8) * 2;
        CP16(st_base + STG_K + so, kg + go);
        CP16(st_base + STG_V + so, vg + go);
    }
}

// ============================================================================
// Kernel 1: 296 CTAs (128 thr, occ 2), warp-granular load balancing.
// Each warp owns an independent 32-q-row group of the CTA's batch (3-4
// groups per CTA); K/V tiles shared via smem. fp16 GEMMs, 4-stage cp.async.
// ============================================================================
__global__ void __launch_bounds__(128, 2)
attn_mma_kernel(const float* __restrict__ q,
                float* __restrict__ ctx)
{
    extern __shared__ char smem[];
    const uint32_t sb = smem_u32(smem);
    const uint32_t Q16 = sb + SM_Q16;

    const int t   = threadIdx.x;
    const int wid = t >> 5;
    const int lid = t & 31;

    const float SL = 0.08838834764831845f * 1.4426950408889634f;

    // ---- batch & warp-group assignment ----
    const int cta = (int)blockIdx.x;
    int b, j, Nc;
    if (cta < 152) { b = cta / 19;        j = cta % 19;         Nc = 19; }
    else           { b = 8 + (cta - 152) / 18; j = (cta - 152) % 18; Nc = 18; }
    const int g_idx  = j + wid * Nc;          // warp-group within batch
    const bool valid = (g_idx < 64);
    const int m_base = g_idx * 32;            // first q-row of this warp's group

    const size_t bL  = (size_t)b * L_;
    const float* qb  = q + bL * D_;
    const size_t kvb = bL * D_;

    // ldmatrix per-lane base offsets; warp uses Q16 rows [32*wid, 32*wid+32)
    const uint32_t q_off0 = (uint32_t)(wid * 32 + (lid & 15)) * STRB + (uint32_t)(lid >> 4) * 16;
    const uint32_t q_off1 = q_off0 + 16u * STRB;
    const uint32_t k_off  = (uint32_t)((lid & 7) + ((lid >> 4) << 3)) * STRB
                          + (uint32_t)((lid >> 3) & 1) * 16;
    const uint32_t v_off  = (uint32_t)((lid & 7) + (((lid >> 3) & 1) << 3)) * STRB
                          + (uint32_t)(lid >> 4) * 16;

    const int start = (cta & 3) << 4;   // tile-order stagger: 0,16,32,48

    #pragma unroll
    for (int pi = 0; pi < 3; ++pi) {
        const int ptile = (start + pi) & (NTILES - 1);
        prefetch_tile(sb + SM_STAGE + (uint32_t)pi * STG_BYTES,
                      kvb + (size_t)(ptile * NT) * D_, t);
        CP_COMMIT();
    }

    // ---- Q load/convert (pre-scaled): each lane loads one row of its group ----
    if (valid) {
        const float4* src = (const float4*)(qb + (size_t)(m_base + lid) * D_);
        char* dh = smem + SM_Q16 + (wid * 32 + lid) * STRB;
        #pragma unroll
        for (int cc = 0; cc < 16; ++cc) {
            const float4 x0 = src[2 * cc];
            const float4 x1 = src[2 * cc + 1];
            uint4 H;
            H.x = cvt_h2(x0.x * SL, x0.y * SL);
            H.y = cvt_h2(x0.z * SL, x0.w * SL);
            H.z = cvt_h2(x1.x * SL, x1.y * SL);
            H.w = cvt_h2(x1.z * SL, x1.w * SL);
            *(uint4*)(dh + cc * 16) = H;
        }
    }

    float C[2][16][4];
    #pragma unroll
    for (int mf = 0; mf < 2; ++mf)
        #pragma unroll
        for (int f = 0; f < 16; ++f)
            #pragma unroll
            for (int e = 0; e < 4; ++e) C[mf][f][e] = 0.0f;
    float rs[2][2] = {{0.f, 0.f}, {0.f, 0.f}};

    for (int i = 0; i < NTILES; ++i) {
        const int tile = (start + i) & (NTILES - 1);
        const int key0 = tile * NT;
        const uint32_t stg = sb + SM_STAGE + (uint32_t)(i & 3) * STG_BYTES;

        CP_WAIT(2);
        __syncthreads();

        if (i + 3 < NTILES) {
            const int ntile = (start + i + 3) & (NTILES - 1);
            prefetch_tile(sb + SM_STAGE + (uint32_t)((i + 3) & 3) * STG_BYTES,
                          kvb + (size_t)(ntile * NT) * D_, t);
        }
        CP_COMMIT();

        if (!valid) continue;   // barriers/prefetch done; skip compute

        const uint32_t KHI = stg + STG_K;
        const uint32_t VHI = stg + STG_V;

        // ---- QK ----
        float S[2][4][4];
        #pragma unroll
        for (int mf = 0; mf < 2; ++mf)
            #pragma unroll
            for (int f = 0; f < 4; ++f)
                #pragma unroll
                for (int e = 0; e < 4; ++e) S[mf][f][e] = 0.0f;

        #pragma unroll
        for (int ks = 0; ks < 8; ++ks) {
            uint32_t a0[4], a1[4], bh[8];
            LDSM4(a0[0], a0[1], a0[2], a0[3], Q16 + q_off0 + ks * 32);
            LDSM4(a1[0], a1[1], a1[2], a1[3], Q16 + q_off1 + ks * 32);
            #pragma unroll
            for (int jj = 0; jj < 2; ++jj)
                LDSM4(bh[4*jj], bh[4*jj+1], bh[4*jj+2], bh[4*jj+3],
                      KHI + k_off + (uint32_t)jj * (16 * STRB) + ks * 32);
            #pragma unroll
            for (int jj = 0; jj < 2; ++jj) {
                MMA_F16(S[0][2*jj],   a0[0], a0[1], a0[2], a0[3], bh[4*jj],   bh[4*jj+1]);
                MMA_F16(S[0][2*jj+1], a0[0], a0[1], a0[2], a0[3], bh[4*jj+2], bh[4*jj+3]);
                MMA_F16(S[1][2*jj],   a1[0], a1[1], a1[2], a1[3], bh[4*jj],   bh[4*jj+1]);
                MMA_F16(S[1][2*jj+1], a1[0], a1[1], a1[2], a1[3], bh[4*jj+2], bh[4*jj+3]);
            }
        }

        // ---- exp + fp16 scratch write + pack P16 ----
        uint32_t PH[2][2][4];
        #pragma unroll
        for (int mf = 0; mf < 2; ++mf) {
            uint32_t* prow = g_pscr
                + (((size_t)(bL + m_base + 16 * mf + (lid >> 2))) * L_
                   + key0 + 2 * (lid & 3)) / 2;
            #pragma unroll
            for (int f = 0; f < 4; ++f) {
                const float p0 = ex2(S[mf][f][0]);
                const float p1 = ex2(S[mf][f][1]);
                const float p2 = ex2(S[mf][f][2]);
                const float p3 = ex2(S[mf][f][3]);
                rs[mf][0] += p0 + p1;
                rs[mf][1] += p2 + p3;
                const int ks = f >> 1;
                const int hh = (f & 1) * 2;
                PH[mf][ks][hh]     = cvt_h2(p0, p1);
                PH[mf][ks][hh + 1] = cvt_h2(p2, p3);
                prow[4 * f]          = PH[mf][ks][hh];
                prow[4 * L_ + 4 * f] = PH[mf][ks][hh + 1];
            }
        }

        // ---- PV ----
        #pragma unroll
        for (int ks = 0; ks < 2; ++ks) {
            uint32_t vf[32];
            #pragma unroll
            for (int jj = 0; jj < 8; ++jj)
                LDSM4T(vf[4*jj], vf[4*jj+1], vf[4*jj+2], vf[4*jj+3],
                       VHI + v_off + (uint32_t)ks * (16 * STRB) + jj * 32);
            #pragma unroll
            for (int jj = 0; jj < 8; ++jj) {
                MMA_F16(C[0][2*jj],   PH[0][ks][0], PH[0][ks][1], PH[0][ks][2], PH[0][ks][3], vf[4*jj],   vf[4*jj+1]);
                MMA_F16(C[0][2*jj+1], PH[0][ks][0], PH[0][ks][1], PH[0][ks][2], PH[0][ks][3], vf[4*jj+2], vf[4*jj+3]);
                MMA_F16(C[1][2*jj],   PH[1][ks][0], PH[1][ks][1], PH[1][ks][2], PH[1][ks][3], vf[4*jj],   vf[4*jj+1]);
                MMA_F16(C[1][2*jj+1], PH[1][ks][0], PH[1][ks][1], PH[1][ks][2], PH[1][ks][3], vf[4*jj+2], vf[4*jj+3]);
            }
        }
    }

    if (!valid) return;

    // ---- row sums + normalize ctx + store inv sums ----
    #pragma unroll
    for (int mf = 0; mf < 2; ++mf) {
        float r0 = rs[mf][0], r1 = rs[mf][1];
        r0 += __shfl_xor_sync(0xffffffffu, r0, 1);
        r0 += __shfl_xor_sync(0xffffffffu, r0, 2);
        r1 += __shfl_xor_sync(0xffffffffu, r1, 1);
        r1 += __shfl_xor_sync(0xffffffffu, r1, 2);
        const float inv0 = 1.0f / r0;
        const float inv1 = 1.0f / r1;

        const int row0 = m_base + 16 * mf + (lid >> 2);
        if ((lid & 3) == 0) {
            g_inv[bL + row0]     = inv0;
            g_inv[bL + row0 + 8] = inv1;
        }

        float* crow = ctx + ((size_t)(bL + row0)) * D_ + 2 * (lid & 3);
        #pragma unroll
        for (int f = 0; f < 16; ++f) {
            *(float2*)(crow + 8 * f)          = make_float2(C[mf][f][0] * inv0, C[mf][f][1] * inv0);
            *(float2*)(crow + 8 * D_ + 8 * f) = make_float2(C[mf][f][2] * inv1, C[mf][f][3] * inv1);
        }
    }
}

// ============================================================================
// Kernel 2: streaming normalize: probs = fp16_scratch * inv[row] -> fp32.
// ~57us at ~80% DRAM roofline.
// ============================================================================
__global__ void __launch_bounds__(256)
norm_probs_kernel(float* __restrict__ probs)
{
    const size_t rowi = blockIdx.x;
    const int t = threadIdx.x;
    const float inv = g_inv[rowi];

    const uint4 d = ((const uint4*)(g_pscr + rowi * (L_ / 2)))[t];
    float2 f0 = __half22float2(*(const __half2*)&d.x);
    float2 f1 = __half22float2(*(const __half2*)&d.y);
    float2 f2 = __half22float2(*(const __half2*)&d.z);
    float2 f3 = __half22float2(*(const __half2*)&d.w);

    float4 o0, o1;
    o0.x = f0.x * inv; o0.y = f0.y * inv; o0.z = f1.x * inv; o0.w = f1.y * inv;
    o1.x = f2.x * inv; o1.y = f2.y * inv; o1.z = f3.x * inv; o1.w = f3.y * inv;

    float* drow = probs + rowi * (size_t)L_ + t * 8;
    *(float4*)(drow)     = o0;
    *(float4*)(drow + 4) = o1;
}

extern "C" void kernel_launch(void* const* d_in, const int* in_sizes, int n_in,
                              void* d_out, int out_size)
{
    const float* q = (const float*)d_in[0];
    const float* k = (const float*)d_in[1];
    const float* v = (const float*)d_in[2];

    float* out   = (float*)d_out;
    float* ctx   = out;
    float* probs = out + (size_t)B_ * L_ * D_;

    cudaFuncSetAttribute(attn_mma_kernel,
                         cudaFuncAttributeMaxDynamicSharedMemorySize, SMEM_BYTES);

    split_kv_kernel<<<TOT / 4 / 256, 256>>>(k, v);

    attn_mma_kernel<<<NCTAS, 128, SMEM_BYTES>>>(q, ctx);

    norm_probs_kernel<<<B_ * L_, 256>>>(probs);
}

// round 17
// speedup vs baseline: 1.1419x; 1.0013x over previous
#include <cuda_runtime.h>
#include <cuda_fp16.h>
#include <cstdint>

#define B_ 16
#define L_ 2048
#define D_ 128
#define NT 32              // keys per tile
#define NTILES 64
#define NCTAS 296          // 2 per SM, one wave
#define TOT (B_ * L_ * D_)

#define STRB 272           // fp16 tile row stride in BYTES

// smem byte offsets
#define SM_Q16   0         // 128 rows x 272B = 34816 (32 rows per warp)
#define SM_STAGE 34816
#define STG_K    0
#define STG_V    8704
#define STG_BYTES 17408
#define SMEM_BYTES (SM_STAGE + 4 * STG_BYTES)   // 104448 (2 CTAs/SM)

// ---- device scratch ----
__device__ __align__(16) static uint32_t g_k16[TOT / 2];
__device__ __align__(16) static uint32_t g_v16[TOT / 2];
__device__ __align__(16) static uint32_t g_pscr[(size_t)(B_ * L_ / 2) * L_]; // fp16 unnorm p
__device__ __align__(16) static float    g_inv[B_ * L_];   // per-row 1/sum

__device__ __forceinline__ uint32_t smem_u32(const void* p) {
    uint32_t a;
    asm("{ .reg .u64 t; cvta.to.shared.u64 t, %1; cvt.u32.u64 %0, t; }" : "=r"(a) : "l"(p));
    return a;
}

#define CP16(SA, GA) \
    asm volatile("cp.async.cg.shared.global [%0], [%1], 16;" :: "r"(SA), "l"(GA) : "memory")
#define CP_COMMIT() asm volatile("cp.async.commit_group;" ::: "memory")
#define CP_WAIT(N)  asm volatile("cp.async.wait_group %0;" :: "n"(N) : "memory")

#define LDSM4(R0, R1, R2, R3, ADDR) \
    asm volatile("ldmatrix.sync.aligned.m8n8.x4.shared.b16 {%0,%1,%2,%3}, [%4];" \
        : "=r"(R0), "=r"(R1), "=r"(R2), "=r"(R3) : "r"(ADDR))

#define LDSM4T(R0, R1, R2, R3, ADDR) \
    asm volatile("ldmatrix.sync.aligned.m8n8.x4.trans.shared.b16 {%0,%1,%2,%3}, [%4];" \
        : "=r"(R0), "=r"(R1), "=r"(R2), "=r"(R3) : "r"(ADDR))

#define MMA_F16(D, A0, A1, A2, A3, B0, B1) \
    asm volatile("mma.sync.aligned.m16n8k16.row.col.f32.f16.f16.f32 " \
        "{%0,%1,%2,%3}, {%4,%5,%6,%7}, {%8,%9}, {%0,%1,%2,%3};" \
        : "+f"((D)[0]), "+f"((D)[1]), "+f"((D)[2]), "+f"((D)[3]) \
        : "r"(A0), "r"(A1), "r"(A2), "r"(A3), "r"(B0), "r"(B1))

__device__ __forceinline__ float ex2(float x) {
    float r;
    asm("ex2.approx.f32 %0, %1;" : "=f"(r) : "f"(x));
    return r;
}
__device__ __forceinline__ uint32_t cvt_h2(float x0, float x1) {
    uint32_t d;
    asm("cvt.rn.f16x2.f32 %0, %1, %2;" : "=r"(d) : "f"(x1), "f"(x0));
    return d;
}
// streaming (no L2 allocate preference) 32-bit global store
__device__ __forceinline__ void stg_cs(uint32_t* p, uint32_t v) {
    asm volatile("st.global.cs.u32 [%0], %1;"
                 :: "l"(__cvta_generic_to_global(p)), "r"(v) : "memory");
}
// streaming v4 load / store
__device__ __forceinline__ uint4 ldg_cs4(const uint4* p) {
    uint4 d;
    asm volatile("ld.global.cs.v4.u32 {%0,%1,%2,%3}, [%4];"
                 : "=r"(d.x), "=r"(d.y), "=r"(d.z), "=r"(d.w)
                 : "l"(__cvta_generic_to_global(p)));
    return d;
}
__device__ __forceinline__ void stg_cs4(float4* p, float4 v) {
    asm volatile("st.global.cs.v4.f32 [%0], {%1,%2,%3,%4};"
                 :: "l"(__cvta_generic_to_global(p)),
                    "f"(v.x), "f"(v.y), "f"(v.z), "f"(v.w) : "memory");
}

// ============================================================================
// Kernel 0: convert K and V to fp16 scratch. MLP 8 per thread (~7us).
// ============================================================================
__global__ void __launch_bounds__(256)
split_kv_kernel(const float* __restrict__ k, const float* __restrict__ v)
{
    const size_t base = ((size_t)blockIdx.x * 256 + threadIdx.x) * 4;  // float4 idx
    float4 kx[4], vx[4];
    #pragma unroll
    for (int j = 0; j < 4; ++j) kx[j] = ((const float4*)k)[base + j];
    #pragma unroll
    for (int j = 0; j < 4; ++j) vx[j] = ((const float4*)v)[base + j];
    #pragma unroll
    for (int j = 0; j < 4; ++j) {
        uint2 kh, vh;
        kh.x = cvt_h2(kx[j].x, kx[j].y);  kh.y = cvt_h2(kx[j].z, kx[j].w);
        vh.x = cvt_h2(vx[j].x, vx[j].y);  vh.y = cvt_h2(vx[j].z, vx[j].w);
        ((uint2*)g_k16)[base + j] = kh;
        ((uint2*)g_v16)[base + j] = vh;
    }
}

// prefetch one 32-key tile (K16,V16): 512 chunks x 2 tensors, 8/thread
__device__ __forceinline__ void prefetch_tile(uint32_t st_base, size_t gelem, int t)
{
    const unsigned long long kg = (unsigned long long)__cvta_generic_to_global(g_k16);
    const unsigned long long vg = (unsigned long long)__cvta_generic_to_global(g_v16);
    #pragma unroll
    for (int j = 0; j < 4; ++j) {
        const int c   = t + j * 128;
        const int row = c >> 4;
        const int col = c & 15;
        const uint32_t so = (uint32_t)row * STRB + (uint32_t)col * 16;
        const unsigned long long go = ((unsigned long long)(gelem + (size_t)row * D_) + col * 8) * 2;
        CP16(st_base + STG_K + so, kg + go);
        CP16(st_base + STG_V + so, vg + go);
    }
}

// ============================================================================
// Kernel 1: 296 CTAs (128 thr, occ 2), warp-granular load balancing.
// Each warp owns an independent 32-q-row group of the CTA's batch.
// fp16 GEMMs, 4-stage cp.async, 1 barrier/tile. pscr stores streamed (.cs).
// ============================================================================
__global__ void __launch_bounds__(128, 2)
attn_mma_kernel(const float* __restrict__ q,
                float* __restrict__ ctx)
{
    extern __shared__ char smem[];
    const uint32_t sb = smem_u32(smem);
    const uint32_t Q16 = sb + SM_Q16;

    const int t   = threadIdx.x;
    const int wid = t >> 5;
    const int lid = t & 31;

    const float SL = 0.08838834764831845f * 1.4426950408889634f;

    // ---- batch & warp-group assignment ----
    const int cta = (int)blockIdx.x;
    int b, j, Nc;
    if (cta < 152) { b = cta / 19;        j = cta % 19;         Nc = 19; }
    else           { b = 8 + (cta - 152) / 18; j = (cta - 152) % 18; Nc = 18; }
    const int g_idx  = j + wid * Nc;
    const bool valid = (g_idx < 64);
    const int m_base = g_idx * 32;

    const size_t bL  = (size_t)b * L_;
    const float* qb  = q + bL * D_;
    const size_t kvb = bL * D_;

    const uint32_t q_off0 = (uint32_t)(wid * 32 + (lid & 15)) * STRB + (uint32_t)(lid >> 4) * 16;
    const uint32_t q_off1 = q_off0 + 16u * STRB;
    const uint32_t k_off  = (uint32_t)((lid & 7) + ((lid >> 4) << 3)) * STRB
                          + (uint32_t)((lid >> 3) & 1) * 16;
    const uint32_t v_off  = (uint32_t)((lid & 7) + (((lid >> 3) & 1) << 3)) * STRB
                          + (uint32_t)(lid >> 4) * 16;

    const int start = (cta & 3) << 4;

    #pragma unroll
    for (int pi = 0; pi < 3; ++pi) {
        const int ptile = (start + pi) & (NTILES - 1);
        prefetch_tile(sb + SM_STAGE + (uint32_t)pi * STG_BYTES,
                      kvb + (size_t)(ptile * NT) * D_, t);
        CP_COMMIT();
    }

    if (valid) {
        const float4* src = (const float4*)(qb + (size_t)(m_base + lid) * D_);
        char* dh = smem + SM_Q16 + (wid * 32 + lid) * STRB;
        #pragma unroll
        for (int cc = 0; cc < 16; ++cc) {
            const float4 x0 = src[2 * cc];
            const float4 x1 = src[2 * cc + 1];
            uint4 H;
            H.x = cvt_h2(x0.x * SL, x0.y * SL);
            H.y = cvt_h2(x0.z * SL, x0.w * SL);
            H.z = cvt_h2(x1.x * SL, x1.y * SL);
            H.w = cvt_h2(x1.z * SL, x1.w * SL);
            *(uint4*)(dh + cc * 16) = H;
        }
    }

    float C[2][16][4];
    #pragma unroll
    for (int mf = 0; mf < 2; ++mf)
        #pragma unroll
        for (int f = 0; f < 16; ++f)
            #pragma unroll
            for (int e = 0; e < 4; ++e) C[mf][f][e] = 0.0f;
    float rs[2][2] = {{0.f, 0.f}, {0.f, 0.f}};

    for (int i = 0; i < NTILES; ++i) {
        const int tile = (start + i) & (NTILES - 1);
        const int key0 = tile * NT;
        const uint32_t stg = sb + SM_STAGE + (uint32_t)(i & 3) * STG_BYTES;

        CP_WAIT(2);
        __syncthreads();

        if (i + 3 < NTILES) {
            const int ntile = (start + i + 3) & (NTILES - 1);
            prefetch_tile(sb + SM_STAGE + (uint32_t)((i + 3) & 3) * STG_BYTES,
                          kvb + (size_t)(ntile * NT) * D_, t);
        }
        CP_COMMIT();

        if (!valid) continue;

        const uint32_t KHI = stg + STG_K;
        const uint32_t VHI = stg + STG_V;

        // ---- QK ----
        float S[2][4][4];
        #pragma unroll
        for (int mf = 0; mf < 2; ++mf)
            #pragma unroll
            for (int f = 0; f < 4; ++f)
                #pragma unroll
                for (int e = 0; e < 4; ++e) S[mf][f][e] = 0.0f;

        #pragma unroll
        for (int ks = 0; ks < 8; ++ks) {
            uint32_t a0[4], a1[4], bh[8];
            LDSM4(a0[0], a0[1], a0[2], a0[3], Q16 + q_off0 + ks * 32);
            LDSM4(a1[0], a1[1], a1[2], a1[3], Q16 + q_off1 + ks * 32);
            #pragma unroll
            for (int jj = 0; jj < 2; ++jj)
                LDSM4(bh[4*jj], bh[4*jj+1], bh[4*jj+2], bh[4*jj+3],
                      KHI + k_off + (uint32_t)jj * (16 * STRB) + ks * 32);
            #pragma unroll
            for (int jj = 0; jj < 2; ++jj) {
                MMA_F16(S[0][2*jj],   a0[0], a0[1], a0[2], a0[3], bh[4*jj],   bh[4*jj+1]);
                MMA_F16(S[0][2*jj+1], a0[0], a0[1], a0[2], a0[3], bh[4*jj+2], bh[4*jj+3]);
                MMA_F16(S[1][2*jj],   a1[0], a1[1], a1[2], a1[3], bh[4*jj],   bh[4*jj+1]);
                MMA_F16(S[1][2*jj+1], a1[0], a1[1], a1[2], a1[3], bh[4*jj+2], bh[4*jj+3]);
            }
        }

        // ---- exp + streamed fp16 scratch write + pack P16 ----
        uint32_t PH[2][2][4];
        #pragma unroll
        for (int mf = 0; mf < 2; ++mf) {
            uint32_t* prow = g_pscr
                + (((size_t)(bL + m_base + 16 * mf + (lid >> 2))) * L_
                   + key0 + 2 * (lid & 3)) / 2;
            #pragma unroll
            for (int f = 0; f < 4; ++f) {
                const float p0 = ex2(S[mf][f][0]);
                const float p1 = ex2(S[mf][f][1]);
                const float p2 = ex2(S[mf][f][2]);
                const float p3 = ex2(S[mf][f][3]);
                rs[mf][0] += p0 + p1;
                rs[mf][1] += p2 + p3;
                const int ks = f >> 1;
                const int hh = (f & 1) * 2;
                PH[mf][ks][hh]     = cvt_h2(p0, p1);
                PH[mf][ks][hh + 1] = cvt_h2(p2, p3);
                stg_cs(prow + 4 * f,          PH[mf][ks][hh]);
                stg_cs(prow + 4 * L_ + 4 * f, PH[mf][ks][hh + 1]);
            }
        }

        // ---- PV ----
        #pragma unroll
        for (int ks = 0; ks < 2; ++ks) {
            uint32_t vf[32];
            #pragma unroll
            for (int jj = 0; jj < 8; ++jj)
                LDSM4T(vf[4*jj], vf[4*jj+1], vf[4*jj+2], vf[4*jj+3],
                       VHI + v_off + (uint32_t)ks * (16 * STRB) + jj * 32);
            #pragma unroll
            for (int jj = 0; jj < 8; ++jj) {
                MMA_F16(C[0][2*jj],   PH[0][ks][0], PH[0][ks][1], PH[0][ks][2], PH[0][ks][3], vf[4*jj],   vf[4*jj+1]);
                MMA_F16(C[0][2*jj+1], PH[0][ks][0], PH[0][ks][1], PH[0][ks][2], PH[0][ks][3], vf[4*jj+2], vf[4*jj+3]);
                MMA_F16(C[1][2*jj],   PH[1][ks][0], PH[1][ks][1], PH[1][ks][2], PH[1][ks][3], vf[4*jj],   vf[4*jj+1]);
                MMA_F16(C[1][2*jj+1], PH[1][ks][0], PH[1][ks][1], PH[1][ks][2], PH[1][ks][3], vf[4*jj+2], vf[4*jj+3]);
            }
        }
    }

    if (!valid) return;

    // ---- row sums + normalize ctx + store inv sums ----
    #pragma unroll
    for (int mf = 0; mf < 2; ++mf) {
        float r0 = rs[mf][0], r1 = rs[mf][1];
        r0 += __shfl_xor_sync(0xffffffffu, r0, 1);
        r0 += __shfl_xor_sync(0xffffffffu, r0, 2);
        r1 += __shfl_xor_sync(0xffffffffu, r1, 1);
        r1 += __shfl_xor_sync(0xffffffffu, r1, 2);
        const float inv0 = 1.0f / r0;
        const float inv1 = 1.0f / r1;

        const int row0 = m_base + 16 * mf + (lid >> 2);
        if ((lid & 3) == 0) {
            g_inv[bL + row0]     = inv0;
            g_inv[bL + row0 + 8] = inv1;
        }

        float* crow = ctx + ((size_t)(bL + row0)) * D_ + 2 * (lid & 3);
        #pragma unroll
        for (int f = 0; f < 16; ++f) {
            *(float2*)(crow + 8 * f)          = make_float2(C[mf][f][0] * inv0, C[mf][f][1] * inv0);
            *(float2*)(crow + 8 * D_ + 8 * f) = make_float2(C[mf][f][2] * inv1, C[mf][f][3] * inv1);
        }
    }
}

// ============================================================================
// Kernel 2: streaming normalize: probs = fp16_scratch * inv[row] -> fp32.
// One block per 2 rows (MLP 2/thread), streaming loads/stores.
// ============================================================================
__global__ void __launch_bounds__(256)
norm_probs_kernel(float* __restrict__ probs)
{
    const size_t row0 = (size_t)blockIdx.x * 2;
    const int t = threadIdx.x;
    const float inv0 = g_inv[row0];
    const float inv1 = g_inv[row0 + 1];

    const uint4 d0 = ldg_cs4((const uint4*)(g_pscr + row0 * (L_ / 2)) + t);
    const uint4 d1 = ldg_cs4((const uint4*)(g_pscr + (row0 + 1) * (L_ / 2)) + t);

    {
        const float2 f0 = __half22float2(*(const __half2*)&d0.x);
        const float2 f1 = __half22float2(*(const __half2*)&d0.y);
        const float2 f2 = __half22float2(*(const __half2*)&d0.z);
        const float2 f3 = __half22float2(*(const __half2*)&d0.w);
        float4* drow = (float4*)(probs + row0 * (size_t)L_) + t * 2;
        stg_cs4(drow,     make_float4(f0.x * inv0, f0.y * inv0, f1.x * inv0, f1.y * inv0));
        stg_cs4(drow + 1, make_float4(f2.x * inv0, f2.y * inv0, f3.x * inv0, f3.y * inv0));
    }
    {
        const float2 f0 = __half22float2(*(const __half2*)&d1.x);
        const float2 f1 = __half22float2(*(const __half2*)&d1.y);
        const float2 f2 = __half22float2(*(const __half2*)&d1.z);
        const float2 f3 = __half22float2(*(const __half2*)&d1.w);
        float4* drow = (float4*)(probs + (row0 + 1) * (size_t)L_) + t * 2;
        stg_cs4(drow,     make_float4(f0.x * inv1, f0.y * inv1, f1.x * inv1, f1.y * inv1));
        stg_cs4(drow + 1, make_float4(f2.x * inv1, f2.y * inv1, f3.x * inv1, f3.y * inv1));
    }
}

extern "C" void kernel_launch(void* const* d_in, const int* in_sizes, int n_in,
                              void* d_out, int out_size)
{
    const float* q = (const float*)d_in[0];
    const float* k = (const float*)d_in[1];
    const float* v = (const float*)d_in[2];

    float* out   = (float*)d_out;
    float* ctx   = out;
    float* probs = out + (size_t)B_ * L_ * D_;

    cudaFuncSetAttribute(attn_mma_kernel,
                         cudaFuncAttributeMaxDynamicSharedMemorySize, SMEM_BYTES);

    split_kv_kernel<<<TOT / 16 / 256, 256>>>(k, v);

    attn_mma_kernel<<<NCTAS, 128, SMEM_BYTES>>>(q, ctx);

    norm_probs_kernel<<<B_ * L_ / 2, 256>>>(probs);
}